// round 14
// baseline (speedup 1.0000x reference)
#include <cuda_runtime.h>

// TokenEmbedding segment-sum, SINGLE kernel, 4 tokens per block:
//   - warp 0: windowed counting search — ONE 256-int window centered at
//     t0+2 yields all FIVE bounds lo(t0)..lo(t0+4) (counts of <t0..<t0+4
//     from the same loaded registers). Edge-validated; binary-search
//     fallback on the (rare, ~1e-4) miss.
//   - all 128 threads: one L2 prefetch line each = rows t0..t0+3 complete
//     (exact self-covering bijection over the grid), issued before the sync.
//   - streaming: champion shape — 2 float4 cols/thread, 4 tokens processed
//     sequentially reusing the same accumulators; search/sync cost
//     amortized 4x, 8192 blocks.

#define B_DIM 8
#define L_DIM 4096
#define H_DIM 1024
#define H4   (H_DIM / 4)   // 256 float4 per row
#define TB   128           // threads; each owns 2 float4 columns
#define WIN  256           // search window (ints)
#define TPB  4             // tokens per block

__device__ __forceinline__ int lower_bound_i32(const int* __restrict__ a, int n, int key) {
    int lo = 0, hi = n;
    while (lo < hi) {
        int mid = (lo + hi) >> 1;
        if (__ldg(a + mid) < key) lo = mid + 1;
        else                      hi = mid;
    }
    return lo;
}

__global__ __launch_bounds__(TB, 16) void token_segsum_kernel(
    const float* __restrict__ x,      // [B, L, H]
    const int*   __restrict__ w2t,    // [B, L] sorted per row
    float*       __restrict__ out)    // [B, L, H]
{
    const int t0 = blockIdx.x * TPB;  // first of four tokens
    const int b  = blockIdx.y;        // batch

    const float* __restrict__ xb  = x   + (size_t)b * L_DIM * H_DIM;
    const int*   __restrict__ idx = w2t + (size_t)b * L_DIM;

    const int warp = threadIdx.x >> 5;
    const int lane = threadIdx.x & 31;

    __shared__ int s_b[TPB + 1];   // lo(t0) .. lo(t0+4)

    // self-covering L2 prefetch: rows t0..t0+3 = 128 x 128B lines,
    // one line per thread (grid-wide bijection with the rows read later)
    {
        const float* p = xb + (size_t)t0 * H_DIM + threadIdx.x * 32;
        asm volatile("prefetch.global.L2 [%0];" :: "l"(p));
    }

    if (warp == 0) {
        // window centered at t0+2, clamped, 16B-aligned
        int s = t0 + 2 - WIN / 2;
        if (s < 0) s = 0;
        if (s > L_DIM - WIN) s = L_DIM - WIN;
        s &= ~3;

        const int4* wp = reinterpret_cast<const int4*>(idx + s);
        const int4 va = __ldg(wp + 2 * lane);
        const int4 vb = __ldg(wp + 2 * lane + 1);

        int cnt[TPB + 1];
        #pragma unroll
        for (int k = 0; k <= TPB; ++k) {
            const int tk = t0 + k;
            int ck = (va.x < tk) + (va.y < tk) + (va.z < tk) + (va.w < tk)
                   + (vb.x < tk) + (vb.y < tk) + (vb.z < tk) + (vb.w < tk);
            cnt[k] = __reduce_add_sync(0xffffffffu, ck);
        }

        // coverage: left of window all < t0, right of window all >= t0+4
        const int leftv  = __shfl_sync(0xffffffffu, va.x, 0);   // idx[s]
        const int rightv = __shfl_sync(0xffffffffu, vb.w, 31);  // idx[s+WIN-1]
        const bool ok = (s == 0           || leftv  <  t0)
                     && (s + WIN >= L_DIM || rightv >= t0 + TPB);

        if (lane == 0) {
            if (ok) {
                #pragma unroll
                for (int k = 0; k <= TPB; ++k) s_b[k] = s + cnt[k];
            } else {  // rare fallback
                #pragma unroll
                for (int k = 0; k <= TPB; ++k)
                    s_b[k] = lower_bound_i32(idx, L_DIM, t0 + k);
            }
        }
    }
    __syncthreads();

    const int c = threadIdx.x;  // float4 column 0..127 (also owns c+128)
    const float4* __restrict__ rows = reinterpret_cast<const float4*>(xb);

    float4* __restrict__ orow =
        reinterpret_cast<float4*>(out + ((size_t)b * L_DIM + t0) * H_DIM);

    #pragma unroll
    for (int k = 0; k < TPB; ++k) {
        const int lo = s_b[k];
        const int hi = s_b[k + 1];

        float4 a0 = make_float4(0.f, 0.f, 0.f, 0.f);
        float4 a1 = a0;
        for (int w = lo; w < hi; ++w) {
            const float4* r = rows + (size_t)w * H4;
            float4 v0 = __ldcs(r + c);
            float4 v1 = __ldcs(r + c + TB);
            a0.x += v0.x; a0.y += v0.y; a0.z += v0.z; a0.w += v0.w;
            a1.x += v1.x; a1.y += v1.y; a1.z += v1.z; a1.w += v1.w;
        }
        __stcs(orow + (size_t)k * H4 + c,      a0);
        __stcs(orow + (size_t)k * H4 + c + TB, a1);
    }
}

extern "C" void kernel_launch(void* const* d_in, const int* in_sizes, int n_in,
                              void* d_out, int out_size)
{
    const float* x   = (const float*)d_in[0];   // sequence_output [B,L,H] fp32
    const int*   w2t = (const int*)  d_in[1];   // wordpiece_to_token [B,L] int32
    float*       out = (float*)d_out;           // [B,L,H] fp32

    dim3 grid(L_DIM / TPB, B_DIM);
    token_segsum_kernel<<<grid, TB>>>(x, w2t, out);
}

// round 15
// speedup vs baseline: 1.0063x; 1.0063x over previous
#include <cuda_runtime.h>

// TokenEmbedding segment-sum, SINGLE kernel, 2 tokens per block, NO BARRIER:
//   Every warp independently runs the windowed counting search (window is
//   L1-broadcast after the first warp touches it); __reduce_add_sync leaves
//   the three bounds in every lane, so there is no shared memory and no
//   __syncthreads on the critical path — each warp flows straight from
//   search into streaming. Warps 1-2 also issue the self-covering L2
//   prefetch of rows t0,t0+1 before searching (prefetch overlaps search).
//   Streaming: champion shape — 2 float4 cols/thread, 2 tokens sequential,
//   same accumulators, __ldcs/__stcs, regs capped via __launch_bounds__.

#define B_DIM 8
#define L_DIM 4096
#define H_DIM 1024
#define H4   (H_DIM / 4)   // 256 float4 per row
#define TB   128           // threads; each owns 2 float4 columns
#define WIN  256           // search window (ints)

__device__ __forceinline__ int lower_bound_i32(const int* __restrict__ a, int n, int key) {
    int lo = 0, hi = n;
    while (lo < hi) {
        int mid = (lo + hi) >> 1;
        if (__ldg(a + mid) < key) lo = mid + 1;
        else                      hi = mid;
    }
    return lo;
}

__global__ __launch_bounds__(TB, 16) void token_segsum_kernel(
    const float* __restrict__ x,      // [B, L, H]
    const int*   __restrict__ w2t,    // [B, L] sorted per row
    float*       __restrict__ out)    // [B, L, H]
{
    const int t0 = blockIdx.x * 2;  // first of two tokens
    const int b  = blockIdx.y;      // batch

    const float* __restrict__ xb  = x   + (size_t)b * L_DIM * H_DIM;
    const int*   __restrict__ idx = w2t + (size_t)b * L_DIM;

    const int warp = threadIdx.x >> 5;
    const int lane = threadIdx.x & 31;

    // self-covering L2 prefetch of rows t0,t0+1 (64 x 128B lines), issued
    // by warps 1-2 BEFORE their search so it overlaps the window loads.
    if (warp == 1 || warp == 2) {
        const float* p = xb + (size_t)t0 * H_DIM + (threadIdx.x - 32) * 32;
        asm volatile("prefetch.global.L2 [%0];" :: "l"(p));
    }

    // ---- per-warp redundant windowed search (no smem, no barrier) ----
    int s = t0 + 1 - WIN / 2;
    if (s < 0) s = 0;
    if (s > L_DIM - WIN) s = L_DIM - WIN;
    s &= ~3;

    const int4* wp = reinterpret_cast<const int4*>(idx + s);
    const int4 va = __ldg(wp + 2 * lane);
    const int4 vb = __ldg(wp + 2 * lane + 1);

    const int t1 = t0 + 1, t2 = t0 + 2;
    int c0 = (va.x < t0) + (va.y < t0) + (va.z < t0) + (va.w < t0)
           + (vb.x < t0) + (vb.y < t0) + (vb.z < t0) + (vb.w < t0);
    int c1 = (va.x < t1) + (va.y < t1) + (va.z < t1) + (va.w < t1)
           + (vb.x < t1) + (vb.y < t1) + (vb.z < t1) + (vb.w < t1);
    int c2 = (va.x < t2) + (va.y < t2) + (va.z < t2) + (va.w < t2)
           + (vb.x < t2) + (vb.y < t2) + (vb.z < t2) + (vb.w < t2);

    c0 = __reduce_add_sync(0xffffffffu, c0);   // result in every lane
    c1 = __reduce_add_sync(0xffffffffu, c1);
    c2 = __reduce_add_sync(0xffffffffu, c2);

    // coverage: left of window all < t0, right of window all >= t0+2
    const int leftv  = __shfl_sync(0xffffffffu, va.x, 0);   // idx[s]
    const int rightv = __shfl_sync(0xffffffffu, vb.w, 31);  // idx[s+WIN-1]
    const bool ok = (s == 0           || leftv  <  t0)
                 && (s + WIN >= L_DIM || rightv >= t2);

    int b0, b1, b2;
    if (ok) {
        b0 = s + c0; b1 = s + c1; b2 = s + c2;
    } else {  // rare fallback: every lane computes redundantly (L1-hot)
        b0 = lower_bound_i32(idx, L_DIM, t0);
        b1 = lower_bound_i32(idx, L_DIM, t1);
        b2 = lower_bound_i32(idx, L_DIM, t2);
    }

    const int c = threadIdx.x;  // float4 column 0..127 (also owns c+128)
    const float4* __restrict__ rows = reinterpret_cast<const float4*>(xb);

    float4* __restrict__ orow =
        reinterpret_cast<float4*>(out + ((size_t)b * L_DIM + t0) * H_DIM);

    // ---- token t0 ----
    {
        float4 a0 = make_float4(0.f, 0.f, 0.f, 0.f);
        float4 a1 = a0;
        for (int w = b0; w < b1; ++w) {
            const float4* r = rows + (size_t)w * H4;
            float4 v0 = __ldcs(r + c);
            float4 v1 = __ldcs(r + c + TB);
            a0.x += v0.x; a0.y += v0.y; a0.z += v0.z; a0.w += v0.w;
            a1.x += v1.x; a1.y += v1.y; a1.z += v1.z; a1.w += v1.w;
        }
        __stcs(orow + c,      a0);
        __stcs(orow + c + TB, a1);
    }

    // ---- token t0+1 (reuses registers; stores overlap these loads) ----
    {
        float4 a0 = make_float4(0.f, 0.f, 0.f, 0.f);
        float4 a1 = a0;
        for (int w = b1; w < b2; ++w) {
            const float4* r = rows + (size_t)w * H4;
            float4 v0 = __ldcs(r + c);
            float4 v1 = __ldcs(r + c + TB);
            a0.x += v0.x; a0.y += v0.y; a0.z += v0.z; a0.w += v0.w;
            a1.x += v1.x; a1.y += v1.y; a1.z += v1.z; a1.w += v1.w;
        }
        __stcs(orow + H4 + c,      a0);
        __stcs(orow + H4 + c + TB, a1);
    }
}

extern "C" void kernel_launch(void* const* d_in, const int* in_sizes, int n_in,
                              void* d_out, int out_size)
{
    const float* x   = (const float*)d_in[0];   // sequence_output [B,L,H] fp32
    const int*   w2t = (const int*)  d_in[1];   // wordpiece_to_token [B,L] int32
    float*       out = (float*)d_out;           // [B,L,H] fp32

    dim3 grid(L_DIM / 2, B_DIM);
    token_segsum_kernel<<<grid, TB>>>(x, w2t, out);
}

// round 16
// speedup vs baseline: 1.0113x; 1.0049x over previous
#include <cuda_runtime.h>

// TokenEmbedding segment-sum, SINGLE kernel, 2 tokens per block (champion
// R13 shape with the search split across warps):
//   - warps 0/1/2: each loads the same 256-int window (L1 broadcast) and
//     computes ONE boundary count (<t0 / <t0+1 / <t0+2) -> smem. Critical
//     path per warp = 1 count + 1 reduce instead of 3.
//   - warps 1/2 handled search only; warp 3 + spare lanes issue the
//     self-covering L2 prefetch of rows t0,t0+1 (grid-wide bijection).
//   - one __syncthreads, then the champion streaming loop: 128 threads,
//     2 float4 cols each, two tokens sequential, same accumulators,
//     __ldcs/__stcs, regs capped by __launch_bounds__(128,16).

#define B_DIM 8
#define L_DIM 4096
#define H_DIM 1024
#define H4   (H_DIM / 4)   // 256 float4 per row
#define TB   128           // threads; each owns 2 float4 columns
#define WIN  256           // search window (ints)

__device__ __forceinline__ int lower_bound_i32(const int* __restrict__ a, int n, int key) {
    int lo = 0, hi = n;
    while (lo < hi) {
        int mid = (lo + hi) >> 1;
        if (__ldg(a + mid) < key) lo = mid + 1;
        else                      hi = mid;
    }
    return lo;
}

__global__ __launch_bounds__(TB, 16) void token_segsum_kernel(
    const float* __restrict__ x,      // [B, L, H]
    const int*   __restrict__ w2t,    // [B, L] sorted per row
    float*       __restrict__ out)    // [B, L, H]
{
    const int t0 = blockIdx.x * 2;  // first of two tokens
    const int b  = blockIdx.y;      // batch

    const float* __restrict__ xb  = x   + (size_t)b * L_DIM * H_DIM;
    const int*   __restrict__ idx = w2t + (size_t)b * L_DIM;

    const int warp = threadIdx.x >> 5;
    const int lane = threadIdx.x & 31;

    __shared__ int s_b[3];   // {lo(t0), lo(t0+1), lo(t0+2)}

    // self-covering L2 prefetch of rows t0,t0+1: 64 x 128B lines.
    // warp 3 does 2 lines/lane (it has no search work).
    if (warp == 3) {
        const float* p0 = xb + (size_t)t0 * H_DIM + lane * 32;
        const float* p1 = p0 + 32 * 32;
        asm volatile("prefetch.global.L2 [%0];" :: "l"(p0));
        asm volatile("prefetch.global.L2 [%0];" :: "l"(p1));
    }

    if (warp < 3) {
        // window centered between t0 and t0+1, clamped, 16B-aligned
        int s = t0 + 1 - WIN / 2;
        if (s < 0) s = 0;
        if (s > L_DIM - WIN) s = L_DIM - WIN;
        s &= ~3;

        const int4* wp = reinterpret_cast<const int4*>(idx + s);
        const int4 va = __ldg(wp + 2 * lane);
        const int4 vb = __ldg(wp + 2 * lane + 1);

        // this warp's key: t0 + warp
        const int tk = t0 + warp;
        int ck = (va.x < tk) + (va.y < tk) + (va.z < tk) + (va.w < tk)
               + (vb.x < tk) + (vb.y < tk) + (vb.z < tk) + (vb.w < tk);
        ck = __reduce_add_sync(0xffffffffu, ck);

        // coverage: left of window all < t0, right of window all >= t0+2
        const int leftv  = __shfl_sync(0xffffffffu, va.x, 0);   // idx[s]
        const int rightv = __shfl_sync(0xffffffffu, vb.w, 31);  // idx[s+WIN-1]
        const bool ok = (s == 0           || leftv  <  t0)
                     && (s + WIN >= L_DIM || rightv >= t0 + 2);

        if (lane == 0) {
            s_b[warp] = ok ? (s + ck) : lower_bound_i32(idx, L_DIM, tk);
        }
    }
    __syncthreads();

    const int b0 = s_b[0];
    const int b1 = s_b[1];
    const int b2 = s_b[2];

    const int c = threadIdx.x;  // float4 column 0..127 (also owns c+128)
    const float4* __restrict__ rows = reinterpret_cast<const float4*>(xb);

    float4* __restrict__ orow =
        reinterpret_cast<float4*>(out + ((size_t)b * L_DIM + t0) * H_DIM);

    // ---- token t0 ----
    {
        float4 a0 = make_float4(0.f, 0.f, 0.f, 0.f);
        float4 a1 = a0;
        for (int w = b0; w < b1; ++w) {
            const float4* r = rows + (size_t)w * H4;
            float4 v0 = __ldcs(r + c);
            float4 v1 = __ldcs(r + c + TB);
            a0.x += v0.x; a0.y += v0.y; a0.z += v0.z; a0.w += v0.w;
            a1.x += v1.x; a1.y += v1.y; a1.z += v1.z; a1.w += v1.w;
        }
        __stcs(orow + c,      a0);
        __stcs(orow + c + TB, a1);
    }

    // ---- token t0+1 (reuses registers; stores overlap these loads) ----
    {
        float4 a0 = make_float4(0.f, 0.f, 0.f, 0.f);
        float4 a1 = a0;
        for (int w = b1; w < b2; ++w) {
            const float4* r = rows + (size_t)w * H4;
            float4 v0 = __ldcs(r + c);
            float4 v1 = __ldcs(r + c + TB);
            a0.x += v0.x; a0.y += v0.y; a0.z += v0.z; a0.w += v0.w;
            a1.x += v1.x; a1.y += v1.y; a1.z += v1.z; a1.w += v1.w;
        }
        __stcs(orow + H4 + c,      a0);
        __stcs(orow + H4 + c + TB, a1);
    }
}

extern "C" void kernel_launch(void* const* d_in, const int* in_sizes, int n_in,
                              void* d_out, int out_size)
{
    const float* x   = (const float*)d_in[0];   // sequence_output [B,L,H] fp32
    const int*   w2t = (const int*)  d_in[1];   // wordpiece_to_token [B,L] int32
    float*       out = (float*)d_out;           // [B,L,H] fp32

    dim3 grid(L_DIM / 2, B_DIM);
    token_segsum_kernel<<<grid, TB>>>(x, w2t, out);
}

// round 17
// speedup vs baseline: 1.0537x; 1.0419x over previous
#include <cuda_runtime.h>

// TokenEmbedding segment-sum, SINGLE kernel, 2 tokens per block (FINAL):
//   - warp 0: windowed counting search (one 256-int window -> all 3 bounds:
//     counts of <t0, <t0+1, <t0+2 from the same loaded registers), coverage
//     validated via window edge values; binary-search fallback on rare miss.
//   - warps 1-2: self-covering L2 prefetch of rows t0,t0+1 (t<->w bijection
//     over the grid -> every input row prefetched exactly once, overlapping
//     the search latency with the row DRAM fetch).
//   - streaming: 128 threads, 2 float4 cols each, two tokens processed
//     sequentially reusing the same accumulators; __ldcs/__stcs streaming
//     hints; __launch_bounds__(128,16) pins regs <= 32 for ~86% occupancy.
// Converged: hot loop runs at ~5.7 TB/s warm (~ mixed R/W roofline for this
// pattern); all structural variants (TPB=4, barrier-free search, split
// search, PDL, producer/consumer fusion) measured neutral or worse.

#define B_DIM 8
#define L_DIM 4096
#define H_DIM 1024
#define H4   (H_DIM / 4)   // 256 float4 per row
#define TB   128           // threads; each owns 2 float4 columns
#define WIN  256           // search window (ints), +-4 sigma around boundary

__device__ __forceinline__ int lower_bound_i32(const int* __restrict__ a, int n, int key) {
    int lo = 0, hi = n;
    while (lo < hi) {
        int mid = (lo + hi) >> 1;
        if (__ldg(a + mid) < key) lo = mid + 1;
        else                      hi = mid;
    }
    return lo;
}

__global__ __launch_bounds__(TB, 16) void token_segsum_kernel(
    const float* __restrict__ x,      // [B, L, H]
    const int*   __restrict__ w2t,    // [B, L] sorted per row
    float*       __restrict__ out)    // [B, L, H]
{
    const int t0 = blockIdx.x * 2;  // first of two tokens
    const int b  = blockIdx.y;      // batch

    const float* __restrict__ xb  = x   + (size_t)b * L_DIM * H_DIM;
    const int*   __restrict__ idx = w2t + (size_t)b * L_DIM;

    const int warp = threadIdx.x >> 5;
    const int lane = threadIdx.x & 31;

    __shared__ int s_b[3];   // {lo(t0), lo(t0+1), lo(t0+2)}

    if (warp == 1 || warp == 2) {
        // self-covering L2 prefetch of rows t0, t0+1: 64 x 128B lines
        const float* p = xb + (size_t)t0 * H_DIM + (threadIdx.x - 32) * 32;
        asm volatile("prefetch.global.L2 [%0];" :: "l"(p));
    }

    if (warp == 0) {
        // window centered between t0 and t0+1, clamped, 16B-aligned
        int s = t0 + 1 - WIN / 2;
        if (s < 0) s = 0;
        if (s > L_DIM - WIN) s = L_DIM - WIN;
        s &= ~3;

        const int4* wp = reinterpret_cast<const int4*>(idx + s);
        const int4 va = __ldg(wp + 2 * lane);
        const int4 vb = __ldg(wp + 2 * lane + 1);

        const int t1 = t0 + 1, t2 = t0 + 2;
        int c0 = (va.x < t0) + (va.y < t0) + (va.z < t0) + (va.w < t0)
               + (vb.x < t0) + (vb.y < t0) + (vb.z < t0) + (vb.w < t0);
        int c1 = (va.x < t1) + (va.y < t1) + (va.z < t1) + (va.w < t1)
               + (vb.x < t1) + (vb.y < t1) + (vb.z < t1) + (vb.w < t1);
        int c2 = (va.x < t2) + (va.y < t2) + (va.z < t2) + (va.w < t2)
               + (vb.x < t2) + (vb.y < t2) + (vb.z < t2) + (vb.w < t2);

        c0 = __reduce_add_sync(0xffffffffu, c0);
        c1 = __reduce_add_sync(0xffffffffu, c1);
        c2 = __reduce_add_sync(0xffffffffu, c2);

        // coverage: left of window all < t0, right of window all >= t0+2
        const int leftv  = __shfl_sync(0xffffffffu, va.x, 0);   // idx[s]
        const int rightv = __shfl_sync(0xffffffffu, vb.w, 31);  // idx[s+WIN-1]
        const bool ok = (s == 0           || leftv  <  t0)
                     && (s + WIN >= L_DIM || rightv >= t2);

        if (lane == 0) {
            if (ok) {
                s_b[0] = s + c0; s_b[1] = s + c1; s_b[2] = s + c2;
            } else {  // rare fallback
                s_b[0] = lower_bound_i32(idx, L_DIM, t0);
                s_b[1] = lower_bound_i32(idx, L_DIM, t1);
                s_b[2] = lower_bound_i32(idx, L_DIM, t2);
            }
        }
    }
    __syncthreads();

    const int b0 = s_b[0];
    const int b1 = s_b[1];
    const int b2 = s_b[2];

    const int c = threadIdx.x;  // float4 column 0..127 (also owns c+128)
    const float4* __restrict__ rows = reinterpret_cast<const float4*>(xb);

    float4* __restrict__ orow =
        reinterpret_cast<float4*>(out + ((size_t)b * L_DIM + t0) * H_DIM);

    // ---- token t0 ----
    {
        float4 a0 = make_float4(0.f, 0.f, 0.f, 0.f);
        float4 a1 = a0;
        for (int w = b0; w < b1; ++w) {
            const float4* r = rows + (size_t)w * H4;
            float4 v0 = __ldcs(r + c);
            float4 v1 = __ldcs(r + c + TB);
            a0.x += v0.x; a0.y += v0.y; a0.z += v0.z; a0.w += v0.w;
            a1.x += v1.x; a1.y += v1.y; a1.z += v1.z; a1.w += v1.w;
        }
        __stcs(orow + c,      a0);
        __stcs(orow + c + TB, a1);
    }

    // ---- token t0+1 (reuses registers; stores overlap these loads) ----
    {
        float4 a0 = make_float4(0.f, 0.f, 0.f, 0.f);
        float4 a1 = a0;
        for (int w = b1; w < b2; ++w) {
            const float4* r = rows + (size_t)w * H4;
            float4 v0 = __ldcs(r + c);
            float4 v1 = __ldcs(r + c + TB);
            a0.x += v0.x; a0.y += v0.y; a0.z += v0.z; a0.w += v0.w;
            a1.x += v1.x; a1.y += v1.y; a1.z += v1.z; a1.w += v1.w;
        }
        __stcs(orow + H4 + c,      a0);
        __stcs(orow + H4 + c + TB, a1);
    }
}

extern "C" void kernel_launch(void* const* d_in, const int* in_sizes, int n_in,
                              void* d_out, int out_size)
{
    const float* x   = (const float*)d_in[0];   // sequence_output [B,L,H] fp32
    const int*   w2t = (const int*)  d_in[1];   // wordpiece_to_token [B,L] int32
    float*       out = (float*)d_out;           // [B,L,H] fp32

    dim3 grid(L_DIM / 2, B_DIM);
    token_segsum_kernel<<<grid, TB>>>(x, w2t, out);
}